// round 6
// baseline (speedup 1.0000x reference)
#include <cuda_runtime.h>
#include <cstdint>
#include <cmath>

namespace {
constexpr int BATCH = 4, NSEQ = 2048, DIM = 1024, NH = 16, DHD = 64, INNER = 1024;
constexpr int MTOK = BATCH * NSEQ;
constexpr float CEXP = 0.125f * 1.4426950408889634f;
}

__device__ float g_Q[MTOK * INNER];   // [B,H,N,DH]
__device__ float g_K[MTOK * INNER];   // [B,H,N,DH]
__device__ float g_V[MTOK * INNER];   // [B,H,N,DH]
__device__ float g_O[MTOK * INNER];   // [B,N,H*DH]

__device__ __forceinline__ uint32_t f2tf(float x) {
    uint32_t u;
    asm("cvt.rna.tf32.f32 %0, %1;" : "=r"(u) : "f"(x));
    return u;
}
__device__ __forceinline__ float tff(float x) { return __uint_as_float(f2tf(x)); }
__device__ __forceinline__ float4 tf4(float4 v) {
    float4 w;
    w.x = tff(v.x); w.y = tff(v.y); w.z = tff(v.z); w.w = tff(v.w);
    return w;
}
__device__ __forceinline__ uint32_t fbits(float x) { return __float_as_uint(x); }
__device__ __forceinline__ float ex2(float x) {
    float y;
    asm("ex2.approx.ftz.f32 %0, %1;" : "=f"(y) : "f"(x));
    return y;
}

__device__ __forceinline__ void mma_tf32(float* d, const uint32_t* a, uint32_t b0, uint32_t b1) {
    asm volatile(
        "mma.sync.aligned.m16n8k8.row.col.f32.tf32.tf32.f32 "
        "{%0,%1,%2,%3}, {%4,%5,%6,%7}, {%8,%9}, {%0,%1,%2,%3};"
        : "+f"(d[0]), "+f"(d[1]), "+f"(d[2]), "+f"(d[3])
        : "r"(a[0]), "r"(a[1]), "r"(a[2]), "r"(a[3]), "r"(b0), "r"(b1));
}

// ---------------------------------------------------------------------------
// GEMM (unchanged, known-good): C[8192,1024] = X @ W, 128x128x32 tiles
// ---------------------------------------------------------------------------
constexpr int BM = 128, BN = 128, BK = 32;
constexpr int ASTR = BK + 4;
constexpr int BSTR = BN + 8;
constexpr int GEMM_SMEM = (2 * BM * ASTR + 2 * BK * BSTR) * 4;

template <int MODE>
__global__ void __launch_bounds__(256)
gemm_tf32(const float* __restrict__ X,
          const float* __restrict__ W0,
          const float* __restrict__ W1,
          const float* __restrict__ W2,
          const float* __restrict__ bias,
          float* __restrict__ outp)
{
    extern __shared__ float sm[];
    float* As = sm;
    float* Bs = sm + 2 * BM * ASTR;

    const int m0 = blockIdx.y * BM;
    const int n0 = blockIdx.x * BN;

    const float* W;
    float* out;
    if (MODE == 0) {
        if (blockIdx.z == 0)      { W = W0; out = g_Q; }
        else if (blockIdx.z == 1) { W = W1; out = g_K; }
        else                      { W = W2; out = g_V; }
    } else {
        W = W0;
        out = outp;
        X = g_O;
    }

    const int tid  = threadIdx.x;
    const int lane = tid & 31;
    const int wid  = tid >> 5;
    const int wm   = wid >> 2;
    const int wn   = wid & 3;
    const int gr   = lane >> 2;
    const int q4   = lane & 3;

    float acc[4][4][4];
    #pragma unroll
    for (int i = 0; i < 4; i++)
        #pragma unroll
        for (int j = 0; j < 4; j++)
            #pragma unroll
            for (int v = 0; v < 4; v++) acc[i][j][v] = 0.f;

    const int arow = tid >> 3, ac4 = tid & 7;
    const int brow = tid >> 5, bc4 = tid & 31;

    float4 ra[4], rb[4];

    auto load_g = [&](int k0) {
        #pragma unroll
        for (int j = 0; j < 4; j++)
            ra[j] = *(const float4*)(X + (size_t)(m0 + arow + j * 32) * 1024 + k0 + ac4 * 4);
        #pragma unroll
        for (int j = 0; j < 4; j++)
            rb[j] = *(const float4*)(W + (size_t)(k0 + brow + j * 8) * 1024 + n0 + bc4 * 4);
    };
    auto store_s = [&](int buf) {
        float* Ad = As + buf * BM * ASTR;
        float* Bd = Bs + buf * BK * BSTR;
        #pragma unroll
        for (int j = 0; j < 4; j++)
            *(float4*)(Ad + (arow + j * 32) * ASTR + ac4 * 4) = tf4(ra[j]);
        #pragma unroll
        for (int j = 0; j < 4; j++)
            *(float4*)(Bd + (brow + j * 8) * BSTR + bc4 * 4) = tf4(rb[j]);
    };

    load_g(0);
    store_s(0);
    __syncthreads();

    const int NKT = 1024 / BK;
    #pragma unroll 1
    for (int kt = 0; kt < NKT; ++kt) {
        if (kt + 1 < NKT) load_g((kt + 1) * BK);

        const float* Ac = As + (kt & 1) * BM * ASTR;
        const float* Bc = Bs + (kt & 1) * BK * BSTR;

        #pragma unroll
        for (int ks = 0; ks < 4; ++ks) {
            uint32_t af[4][4], bf[4][2];
            #pragma unroll
            for (int mi = 0; mi < 4; mi++) {
                int r = wm * 64 + mi * 16 + gr;
                int c = ks * 8 + q4;
                af[mi][0] = fbits(Ac[r * ASTR + c]);
                af[mi][1] = fbits(Ac[(r + 8) * ASTR + c]);
                af[mi][2] = fbits(Ac[r * ASTR + c + 4]);
                af[mi][3] = fbits(Ac[(r + 8) * ASTR + c + 4]);
            }
            #pragma unroll
            for (int ni = 0; ni < 4; ni++) {
                int cc = wn * 32 + ni * 8 + gr;
                int kk = ks * 8 + q4;
                bf[ni][0] = fbits(Bc[kk * BSTR + cc]);
                bf[ni][1] = fbits(Bc[(kk + 4) * BSTR + cc]);
            }
            #pragma unroll
            for (int mi = 0; mi < 4; mi++)
                #pragma unroll
                for (int ni = 0; ni < 4; ni++)
                    mma_tf32(acc[mi][ni], af[mi], bf[ni][0], bf[ni][1]);
        }

        if (kt + 1 < NKT) store_s((kt + 1) & 1);
        __syncthreads();
    }

    #pragma unroll
    for (int mi = 0; mi < 4; mi++) {
        int r = m0 + wm * 64 + mi * 16 + gr;
        #pragma unroll
        for (int ni = 0; ni < 4; ni++) {
            int c = n0 + wn * 32 + ni * 8 + 2 * q4;
            if (MODE == 0) {
                int b = r >> 11, ntk = r & (NSEQ - 1);
                int h = c >> 6, d = c & 63;
                float* p0 = out + ((size_t)((b * NH + h) * NSEQ + ntk)) * DHD + d;
                float* p1 = out + ((size_t)((b * NH + h) * NSEQ + ntk + 8)) * DHD + d;
                *(float2*)p0 = make_float2(acc[mi][ni][0], acc[mi][ni][1]);
                *(float2*)p1 = make_float2(acc[mi][ni][2], acc[mi][ni][3]);
            } else {
                float2 bv = *(const float2*)(bias + c);
                *(float2*)(out + (size_t)r * DIM + c) =
                    make_float2(acc[mi][ni][0] + bv.x, acc[mi][ni][1] + bv.y);
                *(float2*)(out + (size_t)(r + 8) * DIM + c) =
                    make_float2(acc[mi][ni][2] + bv.x, acc[mi][ni][3] + bv.y);
            }
        }
    }
}

// ---------------------------------------------------------------------------
// Flash attention v2: CTA = 256 query rows (8 warps x two 16-row m-tiles).
// S-phase fused over both m-tiles; P built from S accumulators via shfl
// (no smem round-trip); all fragment loads LDS.64, conflict-free layouts:
//   Q/K: stride 72, 8-col group stores [c0,c4,c1,c5,c2,c6,c3,c7]
//   V:   group G=(key>>3)*4+(key&3), stride 136; word = 136G + 2d + pair
// ---------------------------------------------------------------------------
constexpr int QSTR = 72;
constexpr int KSTR = 72;
constexpr int VG   = 136;
constexpr int FLASH_SMEM = (256 * QSTR + 128 * KSTR + 64 * VG) * 4;  // 145408 B

__global__ void __launch_bounds__(256, 1)
flash_attn()
{
    extern __shared__ float sm[];
    float* Qs = sm;                    // 256 x 72
    float* Ks = Qs + 256 * QSTR;       // 128 x 72
    float* Vp = Ks + 128 * KSTR;       // 64 x 136

    const int bh    = blockIdx.y;
    const int qbase = blockIdx.x * 256;
    const float* Qg = g_Q + ((size_t)bh * NSEQ + qbase) * DHD;
    const float* Kg = g_K + (size_t)bh * NSEQ * DHD;
    const float* Vg = g_V + (size_t)bh * NSEQ * DHD;

    const int tid = threadIdx.x, lane = tid & 31, wid = tid >> 5;
    const int gr = lane >> 2, q4 = lane & 3;
    const int rbase = wid * 32;

    // ---- stage Q once (tf32 + pair permute) ----
    {
        const int r2 = tid >> 1, h = tid & 1;
        #pragma unroll
        for (int rb = 0; rb < 2; rb++) {
            int r = rb * 128 + r2;
            const float* qr = Qg + (size_t)r * DHD;
            #pragma unroll
            for (int g = 0; g < 8; g++) {
                int c0 = g * 8 + 2 * h;
                float2 u = *(const float2*)(qr + c0);
                float2 w = *(const float2*)(qr + c0 + 4);
                *(float4*)(Qs + r * QSTR + g * 8 + 4 * h) =
                    make_float4(tff(u.x), tff(w.x), tff(u.y), tff(w.y));
            }
        }
    }

    float o[2][8][4];
    #pragma unroll
    for (int m = 0; m < 2; m++)
        #pragma unroll
        for (int nt = 0; nt < 8; nt++)
            #pragma unroll
            for (int v = 0; v < 4; v++) o[m][nt][v] = 0.f;
    float mr[2][2] = {{-INFINITY, -INFINITY}, {-INFINITY, -INFINITY}};
    float lr[2][2] = {{0.f, 0.f}, {0.f, 0.f}};

    const int srcA = (lane & ~3) | (q4 >> 1);
    const int srcB = srcA + 2;
    const bool esel = (q4 & 1);

    #pragma unroll 1
    for (int it = 0; it < NSEQ / 128; ++it) {
        const float* Kp = Kg + (size_t)it * 128 * DHD;
        const float* Vq = Vg + (size_t)it * 128 * DHD;

        // stage K (pair permute, stride 72)
        {
            const int r = tid >> 1, h = tid & 1;
            const float* kr = Kp + (size_t)r * DHD;
            #pragma unroll
            for (int g = 0; g < 8; g++) {
                int c0 = g * 8 + 2 * h;
                float2 u = *(const float2*)(kr + c0);
                float2 w = *(const float2*)(kr + c0 + 4);
                *(float4*)(Ks + r * KSTR + g * 8 + 4 * h) =
                    make_float4(tff(u.x), tff(w.x), tff(u.y), tff(w.y));
            }
        }
        // stage V (key-pair interleave, group stride 136)
        {
            const int g = tid >> 5, cp = tid & 31, c = 2 * cp;
            #pragma unroll
            for (int j = 0; j < 8; j++) {
                int G = j * 8 + g;
                int key = (G >> 2) * 8 + (G & 3);
                float2 u = *(const float2*)(Vq + (size_t)key * DHD + c);
                float2 w = *(const float2*)(Vq + (size_t)(key + 4) * DHD + c);
                *(float4*)(Vp + G * VG + 4 * cp) =
                    make_float4(tff(u.x), tff(w.x), tff(u.y), tff(w.y));
            }
        }
        __syncthreads();

        // ---- S = Q K^T, fused over both m-tiles ----
        float s[2][16][4];
        #pragma unroll
        for (int m = 0; m < 2; m++)
            #pragma unroll
            for (int nt = 0; nt < 16; nt++)
                #pragma unroll
                for (int v = 0; v < 4; v++) s[m][nt][v] = 0.f;

        #pragma unroll
        for (int kc = 0; kc < 8; kc++) {
            uint32_t qf[2][4];
            #pragma unroll
            for (int m = 0; m < 2; m++) {
                int r = rbase + m * 16 + gr;
                float2 p0 = *(const float2*)(Qs + r * QSTR + kc * 8 + 2 * q4);
                float2 p1 = *(const float2*)(Qs + (r + 8) * QSTR + kc * 8 + 2 * q4);
                qf[m][0] = fbits(p0.x); qf[m][2] = fbits(p0.y);
                qf[m][1] = fbits(p1.x); qf[m][3] = fbits(p1.y);
            }
            #pragma unroll
            for (int nt = 0; nt < 16; nt++) {
                float2 kb = *(const float2*)(Ks + (nt * 8 + gr) * KSTR + kc * 8 + 2 * q4);
                uint32_t b0 = fbits(kb.x), b1 = fbits(kb.y);
                mma_tf32(s[0][nt], qf[0], b0, b1);
                mma_tf32(s[1][nt], qf[1], b0, b1);
            }
        }

        // ---- online softmax per m-tile ----
        #pragma unroll
        for (int m = 0; m < 2; m++) {
            #pragma unroll
            for (int rr = 0; rr < 2; rr++) {
                const int i0 = 2 * rr;
                float tm = -INFINITY;
                #pragma unroll
                for (int nt = 0; nt < 16; nt++)
                    tm = fmaxf(tm, fmaxf(s[m][nt][i0], s[m][nt][i0 + 1]));
                tm = fmaxf(tm, __shfl_xor_sync(0xffffffffu, tm, 1));
                tm = fmaxf(tm, __shfl_xor_sync(0xffffffffu, tm, 2));
                float mnew  = fmaxf(mr[m][rr], tm);
                float alpha = ex2((mr[m][rr] - mnew) * CEXP);
                mr[m][rr] = mnew;
                float ps = 0.f;
                #pragma unroll
                for (int nt = 0; nt < 16; nt++) {
                    float p0 = ex2((s[m][nt][i0] - mnew) * CEXP);
                    float p1 = ex2((s[m][nt][i0 + 1] - mnew) * CEXP);
                    s[m][nt][i0] = p0; s[m][nt][i0 + 1] = p1;
                    ps += p0 + p1;
                }
                ps += __shfl_xor_sync(0xffffffffu, ps, 1);
                ps += __shfl_xor_sync(0xffffffffu, ps, 2);
                lr[m][rr] = lr[m][rr] * alpha + ps;
                #pragma unroll
                for (int nt = 0; nt < 8; nt++) {
                    o[m][nt][i0] *= alpha;
                    o[m][nt][i0 + 1] *= alpha;
                }
            }
            #pragma unroll
            for (int nt = 0; nt < 16; nt++)
                #pragma unroll
                for (int v = 0; v < 4; v++) s[m][nt][v] = tff(s[m][nt][v]);
        }

        // ---- O += P V; A-frags from S accumulators via shfl ----
        #pragma unroll
        for (int kc = 0; kc < 16; kc++) {
            uint32_t a[2][4];
            #pragma unroll
            for (int m = 0; m < 2; m++) {
                float t0 = __shfl_sync(0xffffffffu, s[m][kc][0], srcA);
                float t1 = __shfl_sync(0xffffffffu, s[m][kc][1], srcA);
                float t2 = __shfl_sync(0xffffffffu, s[m][kc][2], srcA);
                float t3 = __shfl_sync(0xffffffffu, s[m][kc][3], srcA);
                float u0 = __shfl_sync(0xffffffffu, s[m][kc][0], srcB);
                float u1 = __shfl_sync(0xffffffffu, s[m][kc][1], srcB);
                float u2 = __shfl_sync(0xffffffffu, s[m][kc][2], srcB);
                float u3 = __shfl_sync(0xffffffffu, s[m][kc][3], srcB);
                a[m][0] = fbits(esel ? t1 : t0);
                a[m][1] = fbits(esel ? t3 : t2);
                a[m][2] = fbits(esel ? u1 : u0);
                a[m][3] = fbits(esel ? u3 : u2);
            }
            const int G = kc * 4 + q4;
            #pragma unroll
            for (int nt = 0; nt < 8; nt++) {
                float2 vb = *(const float2*)(Vp + G * VG + 2 * (nt * 8 + gr));
                uint32_t b0 = fbits(vb.x), b1 = fbits(vb.y);
                mma_tf32(o[0][nt], a[0], b0, b1);
                mma_tf32(o[1][nt], a[1], b0, b1);
            }
        }
        __syncthreads();
    }

    // ---- epilogue: O /= l -> g_O [B,N,H*DH] ----
    const int b = bh / NH, h = bh % NH;
    float* Og = g_O + ((size_t)(b * NSEQ + qbase)) * INNER + h * DHD;
    #pragma unroll
    for (int m = 0; m < 2; m++) {
        const int r0 = rbase + m * 16 + gr;
        const float inv0 = 1.f / lr[m][0];
        const float inv1 = 1.f / lr[m][1];
        #pragma unroll
        for (int nt = 0; nt < 8; nt++) {
            int d = nt * 8 + 2 * q4;
            *(float2*)(Og + (size_t)r0 * INNER + d) =
                make_float2(o[m][nt][0] * inv0, o[m][nt][1] * inv0);
            *(float2*)(Og + (size_t)(r0 + 8) * INNER + d) =
                make_float2(o[m][nt][2] * inv1, o[m][nt][3] * inv1);
        }
    }
}

// ---------------------------------------------------------------------------
// Launch
// ---------------------------------------------------------------------------
extern "C" void kernel_launch(void* const* d_in, const int* in_sizes, int n_in,
                              void* d_out, int out_size) {
    (void)in_sizes; (void)n_in; (void)out_size;
    const float* x  = (const float*)d_in[0];
    const float* Wq = (const float*)d_in[1];
    const float* Wk = (const float*)d_in[2];
    const float* Wv = (const float*)d_in[3];
    const float* Wo = (const float*)d_in[4];
    const float* bo = (const float*)d_in[5];
    float* out = (float*)d_out;

    cudaFuncSetAttribute(gemm_tf32<0>, cudaFuncAttributeMaxDynamicSharedMemorySize, GEMM_SMEM);
    cudaFuncSetAttribute(gemm_tf32<1>, cudaFuncAttributeMaxDynamicSharedMemorySize, GEMM_SMEM);
    cudaFuncSetAttribute(flash_attn,   cudaFuncAttributeMaxDynamicSharedMemorySize, FLASH_SMEM);

    gemm_tf32<0><<<dim3(INNER / BN, MTOK / BM, 3), 256, GEMM_SMEM>>>(
        x, Wq, Wk, Wv, nullptr, nullptr);
    flash_attn<<<dim3(NSEQ / 256, BATCH * NH), 256, FLASH_SMEM>>>();
    gemm_tf32<1><<<dim3(DIM / BN, MTOK / BM, 1), 256, GEMM_SMEM>>>(
        nullptr, Wo, nullptr, nullptr, bo, out);
}

// round 8
// speedup vs baseline: 1.0281x; 1.0281x over previous
#include <cuda_runtime.h>
#include <cstdint>
#include <cmath>

namespace {
constexpr int BATCH = 4, NSEQ = 2048, DIM = 1024, NH = 16, DHD = 64, INNER = 1024;
constexpr int MTOK = BATCH * NSEQ;
constexpr float CEXP = 0.125f * 1.4426950408889634f;
}

__device__ float g_Q[MTOK * INNER];   // [B,H,N,DH]
__device__ float g_K[MTOK * INNER];   // [B,H,N,DH]
__device__ float g_V[MTOK * INNER];   // [B,H,N,DH]
__device__ float g_O[MTOK * INNER];   // [B,N,H*DH]

__device__ __forceinline__ uint32_t f2tf(float x) {
    uint32_t u;
    asm("cvt.rna.tf32.f32 %0, %1;" : "=r"(u) : "f"(x));
    return u;
}
__device__ __forceinline__ float tff(float x) { return __uint_as_float(f2tf(x)); }
__device__ __forceinline__ float4 tf4(float4 v) {
    float4 w;
    w.x = tff(v.x); w.y = tff(v.y); w.z = tff(v.z); w.w = tff(v.w);
    return w;
}
__device__ __forceinline__ uint32_t fbits(float x) { return __float_as_uint(x); }
__device__ __forceinline__ float ex2(float x) {
    float y;
    asm("ex2.approx.ftz.f32 %0, %1;" : "=f"(y) : "f"(x));
    return y;
}

__device__ __forceinline__ void mma_tf32(float* d, const uint32_t* a, uint32_t b0, uint32_t b1) {
    asm volatile(
        "mma.sync.aligned.m16n8k8.row.col.f32.tf32.tf32.f32 "
        "{%0,%1,%2,%3}, {%4,%5,%6,%7}, {%8,%9}, {%0,%1,%2,%3};"
        : "+f"(d[0]), "+f"(d[1]), "+f"(d[2]), "+f"(d[3])
        : "r"(a[0]), "r"(a[1]), "r"(a[2]), "r"(a[3]), "r"(b0), "r"(b1));
}

// ---------------------------------------------------------------------------
// GEMM (unchanged, known-good): C[8192,1024] = X @ W, 128x128x32 tiles
// ---------------------------------------------------------------------------
constexpr int BM = 128, BN = 128, BK = 32;
constexpr int ASTR = BK + 4;
constexpr int BSTR = BN + 8;
constexpr int GEMM_SMEM = (2 * BM * ASTR + 2 * BK * BSTR) * 4;

template <int MODE>
__global__ void __launch_bounds__(256)
gemm_tf32(const float* __restrict__ X,
          const float* __restrict__ W0,
          const float* __restrict__ W1,
          const float* __restrict__ W2,
          const float* __restrict__ bias,
          float* __restrict__ outp)
{
    extern __shared__ float sm[];
    float* As = sm;
    float* Bs = sm + 2 * BM * ASTR;

    const int m0 = blockIdx.y * BM;
    const int n0 = blockIdx.x * BN;

    const float* W;
    float* out;
    if (MODE == 0) {
        if (blockIdx.z == 0)      { W = W0; out = g_Q; }
        else if (blockIdx.z == 1) { W = W1; out = g_K; }
        else                      { W = W2; out = g_V; }
    } else {
        W = W0;
        out = outp;
        X = g_O;
    }

    const int tid  = threadIdx.x;
    const int lane = tid & 31;
    const int wid  = tid >> 5;
    const int wm   = wid >> 2;
    const int wn   = wid & 3;
    const int gr   = lane >> 2;
    const int q4   = lane & 3;

    float acc[4][4][4];
    #pragma unroll
    for (int i = 0; i < 4; i++)
        #pragma unroll
        for (int j = 0; j < 4; j++)
            #pragma unroll
            for (int v = 0; v < 4; v++) acc[i][j][v] = 0.f;

    const int arow = tid >> 3, ac4 = tid & 7;
    const int brow = tid >> 5, bc4 = tid & 31;

    float4 ra[4], rb[4];

    auto load_g = [&](int k0) {
        #pragma unroll
        for (int j = 0; j < 4; j++)
            ra[j] = *(const float4*)(X + (size_t)(m0 + arow + j * 32) * 1024 + k0 + ac4 * 4);
        #pragma unroll
        for (int j = 0; j < 4; j++)
            rb[j] = *(const float4*)(W + (size_t)(k0 + brow + j * 8) * 1024 + n0 + bc4 * 4);
    };
    auto store_s = [&](int buf) {
        float* Ad = As + buf * BM * ASTR;
        float* Bd = Bs + buf * BK * BSTR;
        #pragma unroll
        for (int j = 0; j < 4; j++)
            *(float4*)(Ad + (arow + j * 32) * ASTR + ac4 * 4) = tf4(ra[j]);
        #pragma unroll
        for (int j = 0; j < 4; j++)
            *(float4*)(Bd + (brow + j * 8) * BSTR + bc4 * 4) = tf4(rb[j]);
    };

    load_g(0);
    store_s(0);
    __syncthreads();

    const int NKT = 1024 / BK;
    #pragma unroll 1
    for (int kt = 0; kt < NKT; ++kt) {
        if (kt + 1 < NKT) load_g((kt + 1) * BK);

        const float* Ac = As + (kt & 1) * BM * ASTR;
        const float* Bc = Bs + (kt & 1) * BK * BSTR;

        #pragma unroll
        for (int ks = 0; ks < 4; ++ks) {
            uint32_t af[4][4], bf[4][2];
            #pragma unroll
            for (int mi = 0; mi < 4; mi++) {
                int r = wm * 64 + mi * 16 + gr;
                int c = ks * 8 + q4;
                af[mi][0] = fbits(Ac[r * ASTR + c]);
                af[mi][1] = fbits(Ac[(r + 8) * ASTR + c]);
                af[mi][2] = fbits(Ac[r * ASTR + c + 4]);
                af[mi][3] = fbits(Ac[(r + 8) * ASTR + c + 4]);
            }
            #pragma unroll
            for (int ni = 0; ni < 4; ni++) {
                int cc = wn * 32 + ni * 8 + gr;
                int kk = ks * 8 + q4;
                bf[ni][0] = fbits(Bc[kk * BSTR + cc]);
                bf[ni][1] = fbits(Bc[(kk + 4) * BSTR + cc]);
            }
            #pragma unroll
            for (int mi = 0; mi < 4; mi++)
                #pragma unroll
                for (int ni = 0; ni < 4; ni++)
                    mma_tf32(acc[mi][ni], af[mi], bf[ni][0], bf[ni][1]);
        }

        if (kt + 1 < NKT) store_s((kt + 1) & 1);
        __syncthreads();
    }

    #pragma unroll
    for (int mi = 0; mi < 4; mi++) {
        int r = m0 + wm * 64 + mi * 16 + gr;
        #pragma unroll
        for (int ni = 0; ni < 4; ni++) {
            int c = n0 + wn * 32 + ni * 8 + 2 * q4;
            if (MODE == 0) {
                int b = r >> 11, ntk = r & (NSEQ - 1);
                int h = c >> 6, d = c & 63;
                float* p0 = out + ((size_t)((b * NH + h) * NSEQ + ntk)) * DHD + d;
                float* p1 = out + ((size_t)((b * NH + h) * NSEQ + ntk + 8)) * DHD + d;
                *(float2*)p0 = make_float2(acc[mi][ni][0], acc[mi][ni][1]);
                *(float2*)p1 = make_float2(acc[mi][ni][2], acc[mi][ni][3]);
            } else {
                float2 bv = *(const float2*)(bias + c);
                *(float2*)(out + (size_t)r * DIM + c) =
                    make_float2(acc[mi][ni][0] + bv.x, acc[mi][ni][1] + bv.y);
                *(float2*)(out + (size_t)(r + 8) * DIM + c) =
                    make_float2(acc[mi][ni][2] + bv.x, acc[mi][ni][3] + bv.y);
            }
        }
    }
}

// ---------------------------------------------------------------------------
// Flash attention v3:
//   CTA = 256 query rows (8 warps x two 16-row m-tiles), key tile = 64.
//   k-relabel trick: PV A-fragment IS the S accumulator (a={s0,s2,s1,s3});
//   V staged with adjacent-key pairs interleaved so the matching B-frag is
//   one conflict-free LDS.64. No shfl, no smem round-trip for P.
//   Registers: s[2][8][4]=64 + o[2][8][4]=64  -> no spills.
//   Layouts (all frag LDS are LDS.64, conflict-free):
//     Q/K: stride 72, 8-col group stored [c0,c4,c1,c5,c2,c6,c3,c7]
//     V:   pair i=(kc*4+q4) covers keys (2i,2i+1); word = i*136 + 2d + slot
// ---------------------------------------------------------------------------
constexpr int QSTR = 72;
constexpr int KSTR = 72;
constexpr int VPS  = 136;
constexpr int KTILE = 64;
constexpr int FLASH_SMEM = (256 * QSTR + KTILE * KSTR + (KTILE / 2) * VPS) * 4;  // 109568 B

__global__ void __launch_bounds__(256, 1)
flash_attn()
{
    extern __shared__ float sm[];
    float* Qs = sm;                        // 256 x 72
    float* Ks = Qs + 256 * QSTR;           // 64 x 72
    float* Vp = Ks + KTILE * KSTR;         // 32 x 136

    const int bh    = blockIdx.y;
    const int qbase = blockIdx.x * 256;
    const float* Qg = g_Q + ((size_t)bh * NSEQ + qbase) * DHD;
    const float* Kg = g_K + (size_t)bh * NSEQ * DHD;
    const float* Vg = g_V + (size_t)bh * NSEQ * DHD;

    const int tid = threadIdx.x, lane = tid & 31, wid = tid >> 5;
    const int gr = lane >> 2, q4 = lane & 3;
    const int rbase = wid * 32;

    // ---- stage Q once (tf32, pair-permuted groups) ----
    {
        const int r2 = tid >> 1, h = tid & 1;   // r2: 0..127
        #pragma unroll
        for (int rb = 0; rb < 2; rb++) {
            int r = rb * 128 + r2;
            const float* qr = Qg + (size_t)r * DHD;
            #pragma unroll
            for (int g = 0; g < 8; g++) {
                int c0 = g * 8 + 2 * h;
                float2 u = *(const float2*)(qr + c0);
                float2 w = *(const float2*)(qr + c0 + 4);
                *(float4*)(Qs + r * QSTR + g * 8 + 4 * h) =
                    make_float4(tff(u.x), tff(w.x), tff(u.y), tff(w.y));
            }
        }
    }

    float o[2][8][4];
    #pragma unroll
    for (int m = 0; m < 2; m++)
        #pragma unroll
        for (int nt = 0; nt < 8; nt++)
            #pragma unroll
            for (int v = 0; v < 4; v++) o[m][nt][v] = 0.f;
    float mr[2][2] = {{-INFINITY, -INFINITY}, {-INFINITY, -INFINITY}};
    float lr[2][2] = {{0.f, 0.f}, {0.f, 0.f}};

    // K staging map: h=tid&1, r=(tid>>1)&63, ghalf=tid>>7 -> groups ghalf*4..+3
    const int ksh = tid & 1, ksr = (tid >> 1) & 63, ksg = (tid >> 7) * 4;
    // V staging map: pair i = tid>>3 (0..31), dq = tid&7
    const int vsi = tid >> 3, vsd = tid & 7;

    #pragma unroll 1
    for (int it = 0; it < NSEQ / KTILE; ++it) {
        const float* Kp = Kg + (size_t)it * KTILE * DHD;
        const float* Vq = Vg + (size_t)it * KTILE * DHD;

        // ---- stage K (64 x 72, pair-permuted) ----
        {
            const float* kr = Kp + (size_t)ksr * DHD;
            #pragma unroll
            for (int j = 0; j < 4; j++) {
                int g = ksg + j;
                int c0 = g * 8 + 2 * ksh;
                float2 u = *(const float2*)(kr + c0);
                float2 w = *(const float2*)(kr + c0 + 4);
                *(float4*)(Ks + ksr * KSTR + g * 8 + 4 * ksh) =
                    make_float4(tff(u.x), tff(w.x), tff(u.y), tff(w.y));
            }
        }
        // ---- stage V (pairs (2i,2i+1) interleaved; word = i*136 + 2d) ----
        {
            const float* v0 = Vq + (size_t)(2 * vsi) * DHD;
            const float* v1 = v0 + DHD;
            #pragma unroll
            for (int j = 0; j < 4; j++) {
                int d0 = j * 16 + vsd * 2;
                float2 u = *(const float2*)(v0 + d0);
                float2 w = *(const float2*)(v1 + d0);
                *(float4*)(Vp + vsi * VPS + 2 * d0) =
                    make_float4(tff(u.x), tff(w.x), tff(u.y), tff(w.y));
            }
        }
        __syncthreads();

        // ---- S = Q K^T over 64 keys, fused over both m-tiles ----
        float s[2][8][4];
        #pragma unroll
        for (int m = 0; m < 2; m++)
            #pragma unroll
            for (int nt = 0; nt < 8; nt++)
                #pragma unroll
                for (int v = 0; v < 4; v++) s[m][nt][v] = 0.f;

        #pragma unroll
        for (int kc = 0; kc < 8; kc++) {
            uint32_t qf[2][4];
            #pragma unroll
            for (int m = 0; m < 2; m++) {
                int r = rbase + m * 16 + gr;
                float2 p0 = *(const float2*)(Qs + r * QSTR + kc * 8 + 2 * q4);
                float2 p1 = *(const float2*)(Qs + (r + 8) * QSTR + kc * 8 + 2 * q4);
                qf[m][0] = fbits(p0.x); qf[m][2] = fbits(p0.y);
                qf[m][1] = fbits(p1.x); qf[m][3] = fbits(p1.y);
            }
            #pragma unroll
            for (int nt = 0; nt < 8; nt++) {
                float2 kb = *(const float2*)(Ks + (nt * 8 + gr) * KSTR + kc * 8 + 2 * q4);
                uint32_t b0 = fbits(kb.x), b1 = fbits(kb.y);
                mma_tf32(s[0][nt], qf[0], b0, b1);
                mma_tf32(s[1][nt], qf[1], b0, b1);
            }
        }

        // ---- online softmax per m-tile (rows gr / gr+8) ----
        #pragma unroll
        for (int m = 0; m < 2; m++) {
            #pragma unroll
            for (int rr = 0; rr < 2; rr++) {
                const int i0 = 2 * rr;
                float tm = -INFINITY;
                #pragma unroll
                for (int nt = 0; nt < 8; nt++)
                    tm = fmaxf(tm, fmaxf(s[m][nt][i0], s[m][nt][i0 + 1]));
                tm = fmaxf(tm, __shfl_xor_sync(0xffffffffu, tm, 1));
                tm = fmaxf(tm, __shfl_xor_sync(0xffffffffu, tm, 2));
                float mnew  = fmaxf(mr[m][rr], tm);
                float alpha = ex2((mr[m][rr] - mnew) * CEXP);
                mr[m][rr] = mnew;
                float ps = 0.f;
                #pragma unroll
                for (int nt = 0; nt < 8; nt++) {
                    float p0 = ex2((s[m][nt][i0] - mnew) * CEXP);
                    float p1 = ex2((s[m][nt][i0 + 1] - mnew) * CEXP);
                    s[m][nt][i0] = p0; s[m][nt][i0 + 1] = p1;
                    ps += p0 + p1;
                }
                ps += __shfl_xor_sync(0xffffffffu, ps, 1);
                ps += __shfl_xor_sync(0xffffffffu, ps, 2);
                lr[m][rr] = lr[m][rr] * alpha + ps;
                #pragma unroll
                for (int nt = 0; nt < 8; nt++) {
                    o[m][nt][i0] *= alpha;
                    o[m][nt][i0 + 1] *= alpha;
                }
            }
        }

        // ---- O += P V with k-relabel pi = [0,2,4,6,1,3,5,7]:
        //      A-frag = {s0, s2, s1, s3} (tf32-rounded), B-frag = V pair LDS.64
        #pragma unroll
        for (int kc = 0; kc < 8; kc++) {
            uint32_t a[2][4];
            #pragma unroll
            for (int m = 0; m < 2; m++) {
                a[m][0] = f2tf(s[m][kc][0]);
                a[m][1] = f2tf(s[m][kc][2]);
                a[m][2] = f2tf(s[m][kc][1]);
                a[m][3] = f2tf(s[m][kc][3]);
            }
            const int ip = kc * 4 + q4;     // V pair index: keys (2q4, 2q4+1) of chunk kc
            #pragma unroll
            for (int nt = 0; nt < 8; nt++) {
                float2 vb = *(const float2*)(Vp + ip * VPS + 2 * (nt * 8 + gr));
                uint32_t b0 = fbits(vb.x), b1 = fbits(vb.y);
                mma_tf32(o[0][nt], a[0], b0, b1);
                mma_tf32(o[1][nt], a[1], b0, b1);
            }
        }
        __syncthreads();
    }

    // ---- epilogue: O /= l -> g_O [B,N,H*DH] ----
    const int b = bh / NH, h = bh % NH;
    float* Og = g_O + ((size_t)(b * NSEQ + qbase)) * INNER + h * DHD;
    #pragma unroll
    for (int m = 0; m < 2; m++) {
        const int r0 = rbase + m * 16 + gr;
        const float inv0 = 1.f / lr[m][0];
        const float inv1 = 1.f / lr[m][1];
        #pragma unroll
        for (int nt = 0; nt < 8; nt++) {
            int d = nt * 8 + 2 * q4;
            *(float2*)(Og + (size_t)r0 * INNER + d) =
                make_float2(o[m][nt][0] * inv0, o[m][nt][1] * inv0);
            *(float2*)(Og + (size_t)(r0 + 8) * INNER + d) =
                make_float2(o[m][nt][2] * inv1, o[m][nt][3] * inv1);
        }
    }
}

// ---------------------------------------------------------------------------
// Launch
// ---------------------------------------------------------------------------
extern "C" void kernel_launch(void* const* d_in, const int* in_sizes, int n_in,
                              void* d_out, int out_size) {
    (void)in_sizes; (void)n_in; (void)out_size;
    const float* x  = (const float*)d_in[0];
    const float* Wq = (const float*)d_in[1];
    const float* Wk = (const float*)d_in[2];
    const float* Wv = (const float*)d_in[3];
    const float* Wo = (const float*)d_in[4];
    const float* bo = (const float*)d_in[5];
    float* out = (float*)d_out;

    cudaFuncSetAttribute(gemm_tf32<0>, cudaFuncAttributeMaxDynamicSharedMemorySize, GEMM_SMEM);
    cudaFuncSetAttribute(gemm_tf32<1>, cudaFuncAttributeMaxDynamicSharedMemorySize, GEMM_SMEM);
    cudaFuncSetAttribute(flash_attn,   cudaFuncAttributeMaxDynamicSharedMemorySize, FLASH_SMEM);

    gemm_tf32<0><<<dim3(INNER / BN, MTOK / BM, 3), 256, GEMM_SMEM>>>(
        x, Wq, Wk, Wv, nullptr, nullptr);
    flash_attn<<<dim3(NSEQ / 256, BATCH * NH), 256, FLASH_SMEM>>>();
    gemm_tf32<1><<<dim3(DIM / BN, MTOK / BM, 1), 256, GEMM_SMEM>>>(
        nullptr, Wo, nullptr, nullptr, bo, out);
}

// round 9
// speedup vs baseline: 1.0433x; 1.0149x over previous
#include <cuda_runtime.h>
#include <cstdint>
#include <cmath>

namespace {
constexpr int BATCH = 4, NSEQ = 2048, DIM = 1024, NH = 16, DHD = 64, INNER = 1024;
constexpr int MTOK = BATCH * NSEQ;
constexpr float CEXP = 0.125f * 1.4426950408889634f;
}

__device__ float g_Q[MTOK * INNER];   // [B,H,N,DH]
__device__ float g_K[MTOK * INNER];   // [B,H,N,DH]
__device__ float g_V[MTOK * INNER];   // [B,H,N,DH]
__device__ float g_O[MTOK * INNER];   // [B,N,H*DH]

__device__ __forceinline__ uint32_t f2tf(float x) {
    uint32_t u;
    asm("cvt.rna.tf32.f32 %0, %1;" : "=r"(u) : "f"(x));
    return u;
}
__device__ __forceinline__ float tff(float x) { return __uint_as_float(f2tf(x)); }
__device__ __forceinline__ float4 tf4(float4 v) {
    float4 w;
    w.x = tff(v.x); w.y = tff(v.y); w.z = tff(v.z); w.w = tff(v.w);
    return w;
}
__device__ __forceinline__ uint32_t fbits(float x) { return __float_as_uint(x); }
__device__ __forceinline__ float ex2(float x) {
    float y;
    asm("ex2.approx.ftz.f32 %0, %1;" : "=f"(y) : "f"(x));
    return y;
}

__device__ __forceinline__ void mma_tf32(float* d, const uint32_t* a, uint32_t b0, uint32_t b1) {
    asm volatile(
        "mma.sync.aligned.m16n8k8.row.col.f32.tf32.tf32.f32 "
        "{%0,%1,%2,%3}, {%4,%5,%6,%7}, {%8,%9}, {%0,%1,%2,%3};"
        : "+f"(d[0]), "+f"(d[1]), "+f"(d[2]), "+f"(d[3])
        : "r"(a[0]), "r"(a[1]), "r"(a[2]), "r"(a[3]), "r"(b0), "r"(b1));
}

// ---------------------------------------------------------------------------
// GEMM (unchanged, known-good): C[8192,1024] = X @ W, 128x128x32 tiles
// ---------------------------------------------------------------------------
constexpr int BM = 128, BN = 128, BK = 32;
constexpr int ASTR = BK + 4;
constexpr int BSTR = BN + 8;
constexpr int GEMM_SMEM = (2 * BM * ASTR + 2 * BK * BSTR) * 4;

template <int MODE>
__global__ void __launch_bounds__(256)
gemm_tf32(const float* __restrict__ X,
          const float* __restrict__ W0,
          const float* __restrict__ W1,
          const float* __restrict__ W2,
          const float* __restrict__ bias,
          float* __restrict__ outp)
{
    extern __shared__ float sm[];
    float* As = sm;
    float* Bs = sm + 2 * BM * ASTR;

    const int m0 = blockIdx.y * BM;
    const int n0 = blockIdx.x * BN;

    const float* W;
    float* out;
    if (MODE == 0) {
        if (blockIdx.z == 0)      { W = W0; out = g_Q; }
        else if (blockIdx.z == 1) { W = W1; out = g_K; }
        else                      { W = W2; out = g_V; }
    } else {
        W = W0;
        out = outp;
        X = g_O;
    }

    const int tid  = threadIdx.x;
    const int lane = tid & 31;
    const int wid  = tid >> 5;
    const int wm   = wid >> 2;
    const int wn   = wid & 3;
    const int gr   = lane >> 2;
    const int q4   = lane & 3;

    float acc[4][4][4];
    #pragma unroll
    for (int i = 0; i < 4; i++)
        #pragma unroll
        for (int j = 0; j < 4; j++)
            #pragma unroll
            for (int v = 0; v < 4; v++) acc[i][j][v] = 0.f;

    const int arow = tid >> 3, ac4 = tid & 7;
    const int brow = tid >> 5, bc4 = tid & 31;

    float4 ra[4], rb[4];

    auto load_g = [&](int k0) {
        #pragma unroll
        for (int j = 0; j < 4; j++)
            ra[j] = *(const float4*)(X + (size_t)(m0 + arow + j * 32) * 1024 + k0 + ac4 * 4);
        #pragma unroll
        for (int j = 0; j < 4; j++)
            rb[j] = *(const float4*)(W + (size_t)(k0 + brow + j * 8) * 1024 + n0 + bc4 * 4);
    };
    auto store_s = [&](int buf) {
        float* Ad = As + buf * BM * ASTR;
        float* Bd = Bs + buf * BK * BSTR;
        #pragma unroll
        for (int j = 0; j < 4; j++)
            *(float4*)(Ad + (arow + j * 32) * ASTR + ac4 * 4) = tf4(ra[j]);
        #pragma unroll
        for (int j = 0; j < 4; j++)
            *(float4*)(Bd + (brow + j * 8) * BSTR + bc4 * 4) = tf4(rb[j]);
    };

    load_g(0);
    store_s(0);
    __syncthreads();

    const int NKT = 1024 / BK;
    #pragma unroll 1
    for (int kt = 0; kt < NKT; ++kt) {
        if (kt + 1 < NKT) load_g((kt + 1) * BK);

        const float* Ac = As + (kt & 1) * BM * ASTR;
        const float* Bc = Bs + (kt & 1) * BK * BSTR;

        #pragma unroll
        for (int ks = 0; ks < 4; ++ks) {
            uint32_t af[4][4], bf[4][2];
            #pragma unroll
            for (int mi = 0; mi < 4; mi++) {
                int r = wm * 64 + mi * 16 + gr;
                int c = ks * 8 + q4;
                af[mi][0] = fbits(Ac[r * ASTR + c]);
                af[mi][1] = fbits(Ac[(r + 8) * ASTR + c]);
                af[mi][2] = fbits(Ac[r * ASTR + c + 4]);
                af[mi][3] = fbits(Ac[(r + 8) * ASTR + c + 4]);
            }
            #pragma unroll
            for (int ni = 0; ni < 4; ni++) {
                int cc = wn * 32 + ni * 8 + gr;
                int kk = ks * 8 + q4;
                bf[ni][0] = fbits(Bc[kk * BSTR + cc]);
                bf[ni][1] = fbits(Bc[(kk + 4) * BSTR + cc]);
            }
            #pragma unroll
            for (int mi = 0; mi < 4; mi++)
                #pragma unroll
                for (int ni = 0; ni < 4; ni++)
                    mma_tf32(acc[mi][ni], af[mi], bf[ni][0], bf[ni][1]);
        }

        if (kt + 1 < NKT) store_s((kt + 1) & 1);
        __syncthreads();
    }

    #pragma unroll
    for (int mi = 0; mi < 4; mi++) {
        int r = m0 + wm * 64 + mi * 16 + gr;
        #pragma unroll
        for (int ni = 0; ni < 4; ni++) {
            int c = n0 + wn * 32 + ni * 8 + 2 * q4;
            if (MODE == 0) {
                int b = r >> 11, ntk = r & (NSEQ - 1);
                int h = c >> 6, d = c & 63;
                float* p0 = out + ((size_t)((b * NH + h) * NSEQ + ntk)) * DHD + d;
                float* p1 = out + ((size_t)((b * NH + h) * NSEQ + ntk + 8)) * DHD + d;
                *(float2*)p0 = make_float2(acc[mi][ni][0], acc[mi][ni][1]);
                *(float2*)p1 = make_float2(acc[mi][ni][2], acc[mi][ni][3]);
            } else {
                float2 bv = *(const float2*)(bias + c);
                *(float2*)(out + (size_t)r * DIM + c) =
                    make_float2(acc[mi][ni][0] + bv.x, acc[mi][ni][1] + bv.y);
                *(float2*)(out + (size_t)(r + 8) * DIM + c) =
                    make_float2(acc[mi][ni][2] + bv.x, acc[mi][ni][3] + bv.y);
            }
        }
    }
}

// ---------------------------------------------------------------------------
// Flash attention v4: 512 threads / 16 warps per CTA (4 warps/SMSP for
// latency hiding), 256 query rows, one 16-row m-tile per warp, key tile 64.
// Same math/layouts as v3 (k-relabel: PV A-frag IS the S accumulator;
// V staged with adjacent-key pairs interleaved; all frag LDS are LDS.64,
// conflict-free):
//   Q/K: stride 72, 8-col group stored [c0,c4,c1,c5,c2,c6,c3,c7]
//   V:   pair i covers keys (2i,2i+1); word = i*136 + 2d + slot
// Registers: s[8][4]=32 + o[8][4]=32 + temps ~ <=128 -> 512 thr fits regfile.
// ---------------------------------------------------------------------------
constexpr int QSTR = 72;
constexpr int KSTR = 72;
constexpr int VPS  = 136;
constexpr int KTILE = 64;
constexpr int FLASH_SMEM = (256 * QSTR + KTILE * KSTR + (KTILE / 2) * VPS) * 4;  // 109568 B

__global__ void __launch_bounds__(512, 1)
flash_attn()
{
    extern __shared__ float sm[];
    float* Qs = sm;                        // 256 x 72
    float* Ks = Qs + 256 * QSTR;           // 64 x 72
    float* Vp = Ks + KTILE * KSTR;         // 32 x 136

    const int bh    = blockIdx.y;
    const int qbase = blockIdx.x * 256;
    const float* Qg = g_Q + ((size_t)bh * NSEQ + qbase) * DHD;
    const float* Kg = g_K + (size_t)bh * NSEQ * DHD;
    const float* Vg = g_V + (size_t)bh * NSEQ * DHD;

    const int tid = threadIdx.x, lane = tid & 31, wid = tid >> 5;  // wid 0..15
    const int gr = lane >> 2, q4 = lane & 3;
    const int rbase = wid * 16;            // one 16-row m-tile per warp

    // ---- stage Q once (tf32, pair-permuted groups); 512 thr: r=tid>>1 ----
    {
        const int r = tid >> 1, h = tid & 1;   // r: 0..255
        const float* qr = Qg + (size_t)r * DHD;
        #pragma unroll
        for (int g = 0; g < 8; g++) {
            int c0 = g * 8 + 2 * h;
            float2 u = *(const float2*)(qr + c0);
            float2 w = *(const float2*)(qr + c0 + 4);
            *(float4*)(Qs + r * QSTR + g * 8 + 4 * h) =
                make_float4(tff(u.x), tff(w.x), tff(u.y), tff(w.y));
        }
    }

    float o[8][4];
    #pragma unroll
    for (int nt = 0; nt < 8; nt++)
        #pragma unroll
        for (int v = 0; v < 4; v++) o[nt][v] = 0.f;
    float mr[2] = {-INFINITY, -INFINITY};
    float lr[2] = {0.f, 0.f};

    // K staging map (512 thr, 1024 float4 stores, 2 per thread):
    //   row = (tid>>1)&63, h = tid&1, groups = (tid>>7)*2 + {0,1}
    const int ksh = tid & 1, ksr = (tid >> 1) & 63, ksg = (tid >> 7) * 2;
    // V staging map (512 thr, 1024 float4 stores, 2 per thread):
    //   pair i = tid>>4 (0..31), dq = tid&15, d0 = j*32 + dq*2
    const int vsi = tid >> 4, vsd = tid & 15;

    #pragma unroll 1
    for (int it = 0; it < NSEQ / KTILE; ++it) {
        const float* Kp = Kg + (size_t)it * KTILE * DHD;
        const float* Vq = Vg + (size_t)it * KTILE * DHD;

        // ---- stage K (64 x 72, pair-permuted) ----
        {
            const float* kr = Kp + (size_t)ksr * DHD;
            #pragma unroll
            for (int j = 0; j < 2; j++) {
                int g = ksg + j;
                int c0 = g * 8 + 2 * ksh;
                float2 u = *(const float2*)(kr + c0);
                float2 w = *(const float2*)(kr + c0 + 4);
                *(float4*)(Ks + ksr * KSTR + g * 8 + 4 * ksh) =
                    make_float4(tff(u.x), tff(w.x), tff(u.y), tff(w.y));
            }
        }
        // ---- stage V (pairs (2i,2i+1) interleaved; word = i*136 + 2d) ----
        {
            const float* v0 = Vq + (size_t)(2 * vsi) * DHD;
            const float* v1 = v0 + DHD;
            #pragma unroll
            for (int j = 0; j < 2; j++) {
                int d0 = j * 32 + vsd * 2;
                float2 u = *(const float2*)(v0 + d0);
                float2 w = *(const float2*)(v1 + d0);
                *(float4*)(Vp + vsi * VPS + 2 * d0) =
                    make_float4(tff(u.x), tff(w.x), tff(u.y), tff(w.y));
            }
        }
        __syncthreads();

        // ---- S = Q K^T over 64 keys ----
        float s[8][4];
        #pragma unroll
        for (int nt = 0; nt < 8; nt++)
            #pragma unroll
            for (int v = 0; v < 4; v++) s[nt][v] = 0.f;

        #pragma unroll
        for (int kc = 0; kc < 8; kc++) {
            uint32_t qf[4];
            {
                int r = rbase + gr;
                float2 p0 = *(const float2*)(Qs + r * QSTR + kc * 8 + 2 * q4);
                float2 p1 = *(const float2*)(Qs + (r + 8) * QSTR + kc * 8 + 2 * q4);
                qf[0] = fbits(p0.x); qf[2] = fbits(p0.y);
                qf[1] = fbits(p1.x); qf[3] = fbits(p1.y);
            }
            #pragma unroll
            for (int nt = 0; nt < 8; nt++) {
                float2 kb = *(const float2*)(Ks + (nt * 8 + gr) * KSTR + kc * 8 + 2 * q4);
                mma_tf32(s[nt], qf, fbits(kb.x), fbits(kb.y));
            }
        }

        // ---- online softmax (rows gr / gr+8) ----
        #pragma unroll
        for (int rr = 0; rr < 2; rr++) {
            const int i0 = 2 * rr;
            float tm = -INFINITY;
            #pragma unroll
            for (int nt = 0; nt < 8; nt++)
                tm = fmaxf(tm, fmaxf(s[nt][i0], s[nt][i0 + 1]));
            tm = fmaxf(tm, __shfl_xor_sync(0xffffffffu, tm, 1));
            tm = fmaxf(tm, __shfl_xor_sync(0xffffffffu, tm, 2));
            float mnew  = fmaxf(mr[rr], tm);
            float alpha = ex2((mr[rr] - mnew) * CEXP);
            mr[rr] = mnew;
            float ps = 0.f;
            #pragma unroll
            for (int nt = 0; nt < 8; nt++) {
                float p0 = ex2((s[nt][i0] - mnew) * CEXP);
                float p1 = ex2((s[nt][i0 + 1] - mnew) * CEXP);
                s[nt][i0] = p0; s[nt][i0 + 1] = p1;
                ps += p0 + p1;
            }
            ps += __shfl_xor_sync(0xffffffffu, ps, 1);
            ps += __shfl_xor_sync(0xffffffffu, ps, 2);
            lr[rr] = lr[rr] * alpha + ps;
            #pragma unroll
            for (int nt = 0; nt < 8; nt++) {
                o[nt][i0] *= alpha;
                o[nt][i0 + 1] *= alpha;
            }
        }

        // ---- O += P V with k-relabel pi = [0,2,4,6,1,3,5,7]:
        //      A-frag = {s0, s2, s1, s3} (tf32-rounded), B-frag = V pair LDS.64
        #pragma unroll
        for (int kc = 0; kc < 8; kc++) {
            uint32_t a[4];
            a[0] = f2tf(s[kc][0]);
            a[1] = f2tf(s[kc][2]);
            a[2] = f2tf(s[kc][1]);
            a[3] = f2tf(s[kc][3]);
            const int ip = kc * 4 + q4;     // V pair: keys (2q4, 2q4+1) of chunk kc
            #pragma unroll
            for (int nt = 0; nt < 8; nt++) {
                float2 vb = *(const float2*)(Vp + ip * VPS + 2 * (nt * 8 + gr));
                mma_tf32(o[nt], a, fbits(vb.x), fbits(vb.y));
            }
        }
        __syncthreads();
    }

    // ---- epilogue: O /= l -> g_O [B,N,H*DH] ----
    const int b = bh / NH, h = bh % NH;
    float* Og = g_O + ((size_t)(b * NSEQ + qbase)) * INNER + h * DHD;
    const int r0 = rbase + gr;
    const float inv0 = 1.f / lr[0];
    const float inv1 = 1.f / lr[1];
    #pragma unroll
    for (int nt = 0; nt < 8; nt++) {
        int d = nt * 8 + 2 * q4;
        *(float2*)(Og + (size_t)r0 * INNER + d) =
            make_float2(o[nt][0] * inv0, o[nt][1] * inv0);
        *(float2*)(Og + (size_t)(r0 + 8) * INNER + d) =
            make_float2(o[nt][2] * inv1, o[nt][3] * inv1);
    }
}

// ---------------------------------------------------------------------------
// Launch
// ---------------------------------------------------------------------------
extern "C" void kernel_launch(void* const* d_in, const int* in_sizes, int n_in,
                              void* d_out, int out_size) {
    (void)in_sizes; (void)n_in; (void)out_size;
    const float* x  = (const float*)d_in[0];
    const float* Wq = (const float*)d_in[1];
    const float* Wk = (const float*)d_in[2];
    const float* Wv = (const float*)d_in[3];
    const float* Wo = (const float*)d_in[4];
    const float* bo = (const float*)d_in[5];
    float* out = (float*)d_out;

    cudaFuncSetAttribute(gemm_tf32<0>, cudaFuncAttributeMaxDynamicSharedMemorySize, GEMM_SMEM);
    cudaFuncSetAttribute(gemm_tf32<1>, cudaFuncAttributeMaxDynamicSharedMemorySize, GEMM_SMEM);
    cudaFuncSetAttribute(flash_attn,   cudaFuncAttributeMaxDynamicSharedMemorySize, FLASH_SMEM);

    gemm_tf32<0><<<dim3(INNER / BN, MTOK / BM, 3), 256, GEMM_SMEM>>>(
        x, Wq, Wk, Wv, nullptr, nullptr);
    flash_attn<<<dim3(NSEQ / 256, BATCH * NH), 512, FLASH_SMEM>>>();
    gemm_tf32<1><<<dim3(DIM / BN, MTOK / BM, 1), 256, GEMM_SMEM>>>(
        nullptr, Wo, nullptr, nullptr, bo, out);
}

// round 13
// speedup vs baseline: 1.1822x; 1.1331x over previous
#include <cuda_runtime.h>
#include <cstdint>
#include <cmath>

namespace {
constexpr int BATCH = 4, NSEQ = 2048, DIM = 1024, NH = 16, DHD = 64, INNER = 1024;
constexpr int MTOK = BATCH * NSEQ;
constexpr float CEXP = 0.125f * 1.4426950408889634f;
}

// Scratch (allocation-free rule: __device__ globals)
__device__ __align__(256) float g_Q[MTOK * INNER];   // [B,H,N,DH]  (tf32-rounded)
__device__ __align__(256) float g_K[MTOK * INNER];   // [B,H,N,DH]  (tf32-rounded)
__device__ __align__(256) float g_V[MTOK * INNER];   // [B,H,N,DH]  (tf32-rounded)
__device__ __align__(256) float g_O[MTOK * INNER];   // [B,N,H*DH]  (tf32-rounded)
__device__ __align__(256) float g_X [MTOK * DIM];    // rna(x)
__device__ __align__(256) float g_Wq[DIM * INNER];   // rna(Wq)
__device__ __align__(256) float g_Wk[DIM * INNER];
__device__ __align__(256) float g_Wv[DIM * INNER];
__device__ __align__(256) float g_Wo[INNER * DIM];

__device__ __forceinline__ uint32_t f2tf(float x) {
    uint32_t u;
    asm("cvt.rna.tf32.f32 %0, %1;" : "=r"(u) : "f"(x));
    return u;
}
__device__ __forceinline__ float tff(float x) { return __uint_as_float(f2tf(x)); }
__device__ __forceinline__ uint32_t fbits(float x) { return __float_as_uint(x); }
__device__ __forceinline__ float ex2(float x) {
    float y;
    asm("ex2.approx.ftz.f32 %0, %1;" : "=f"(y) : "f"(x));
    return y;
}

// D += A(16x8) * B(8x8), tf32 (operands pre-rounded; HW truncation = identity)
__device__ __forceinline__ void mma_tf32(float* d, const uint32_t* a, uint32_t b0, uint32_t b1) {
    asm volatile(
        "mma.sync.aligned.m16n8k8.row.col.f32.tf32.tf32.f32 "
        "{%0,%1,%2,%3}, {%4,%5,%6,%7}, {%8,%9}, {%0,%1,%2,%3};"
        : "+f"(d[0]), "+f"(d[1]), "+f"(d[2]), "+f"(d[3])
        : "r"(a[0]), "r"(a[1]), "r"(a[2]), "r"(a[3]), "r"(b0), "r"(b1));
}

// cp.async helpers
__device__ __forceinline__ void cp16(uint32_t dst, const void* src) {
    asm volatile("cp.async.cg.shared.global [%0], [%1], 16;" :: "r"(dst), "l"(src));
}
__device__ __forceinline__ void cp_commit() { asm volatile("cp.async.commit_group;"); }
template <int N>
__device__ __forceinline__ void cp_wait() { asm volatile("cp.async.wait_group %0;" :: "n"(N)); }

// ---------------------------------------------------------------------------
// Pre-round pass: dst = rna_tf32(src), vectorized
// ---------------------------------------------------------------------------
__global__ void __launch_bounds__(256)
round_tf32(const float* __restrict__ src, float* __restrict__ dst, int n4)
{
    int i = blockIdx.x * 256 + threadIdx.x;
    int stride = gridDim.x * 256;
    for (; i < n4; i += stride) {
        float4 v = ((const float4*)src)[i];
        v.x = tff(v.x); v.y = tff(v.y); v.z = tff(v.z); v.w = tff(v.w);
        ((float4*)dst)[i] = v;
    }
}

// ---------------------------------------------------------------------------
// GEMM v2: C[8192,1024] = X @ W.  CTA 128x128x32, 128 threads (4 warps of
// 64x64).  cp.async 2-stage staging; operands pre-rounded (no cvt in loop).
// MODE 0: QKV projections (blockIdx.z), epilogue rounds outputs.
// MODE 1: out-proj + bias -> d_out.
// ---------------------------------------------------------------------------
constexpr int BM = 128, BN = 128, BK = 32;
constexpr int ASTR = 36;
constexpr int BSTR = 136;
constexpr int GEMM_SMEM = (2 * BM * ASTR + 2 * BK * BSTR) * 4;   // 71680 B

template <int MODE>
__global__ void __launch_bounds__(128)
gemm_tf32(const float* __restrict__ bias, float* __restrict__ outp)
{
    extern __shared__ float sm[];
    float* As = sm;                      // [2][128][36]
    float* Bs = sm + 2 * BM * ASTR;      // [2][32][136]
    const uint32_t As_u = (uint32_t)__cvta_generic_to_shared(As);
    const uint32_t Bs_u = (uint32_t)__cvta_generic_to_shared(Bs);

    const int m0 = blockIdx.y * BM;
    const int n0 = blockIdx.x * BN;

    const float* X;
    const float* W;
    float* out;
    if (MODE == 0) {
        X = g_X;
        if (blockIdx.z == 0)      { W = g_Wq; out = g_Q; }
        else if (blockIdx.z == 1) { W = g_Wk; out = g_K; }
        else                      { W = g_Wv; out = g_V; }
    } else {
        X = g_O;
        W = g_Wo;
        out = outp;
    }

    const int tid  = threadIdx.x;
    const int lane = tid & 31;
    const int wid  = tid >> 5;
    const int wm   = wid >> 1;    // 0..1 (64-row tiles)
    const int wn   = wid & 1;     // 0..1 (64-col tiles)
    const int gr   = lane >> 2;
    const int q4   = lane & 3;

    float acc[4][8][4];
    #pragma unroll
    for (int i = 0; i < 4; i++)
        #pragma unroll
        for (int j = 0; j < 8; j++)
            #pragma unroll
            for (int v = 0; v < 4; v++) acc[i][j][v] = 0.f;

    auto issue = [&](int kt) {
        const int k0 = kt * BK, buf = kt & 1;
        const uint32_t ab = As_u + buf * (BM * ASTR * 4);
        const uint32_t bb = Bs_u + buf * (BK * BSTR * 4);
        #pragma unroll
        for (int j = 0; j < 8; j++) {
            int ch = tid + j * 128;            // 0..1023
            int ar = ch >> 3, ac = ch & 7;     // A: 128 rows x 8 chunks
            cp16(ab + (uint32_t)(ar * ASTR + ac * 4) * 4,
                 X + (size_t)(m0 + ar) * 1024 + k0 + ac * 4);
        }
        #pragma unroll
        for (int j = 0; j < 8; j++) {
            int ch = tid + j * 128;
            int br = ch >> 5, bc = ch & 31;    // B: 32 rows x 32 chunks
            cp16(bb + (uint32_t)(br * BSTR + bc * 4) * 4,
                 W + (size_t)(k0 + br) * 1024 + n0 + bc * 4);
        }
        cp_commit();
    };

    issue(0);

    const int NKT = DIM / BK;   // 32
    #pragma unroll 1
    for (int kt = 0; kt < NKT; ++kt) {
        if (kt + 1 < NKT) { issue(kt + 1); cp_wait<1>(); }
        else              { cp_wait<0>(); }
        __syncthreads();

        const float* Ac = As + (kt & 1) * BM * ASTR;
        const float* Bc = Bs + (kt & 1) * BK * BSTR;

        #pragma unroll
        for (int ks = 0; ks < 4; ++ks) {
            uint32_t af[4][4], bf[8][2];
            #pragma unroll
            for (int mi = 0; mi < 4; mi++) {
                int r = wm * 64 + mi * 16 + gr;
                int c = ks * 8 + q4;
                af[mi][0] = fbits(Ac[r * ASTR + c]);
                af[mi][1] = fbits(Ac[(r + 8) * ASTR + c]);
                af[mi][2] = fbits(Ac[r * ASTR + c + 4]);
                af[mi][3] = fbits(Ac[(r + 8) * ASTR + c + 4]);
            }
            #pragma unroll
            for (int ni = 0; ni < 8; ni++) {
                int cc = wn * 64 + ni * 8 + gr;
                int kk = ks * 8 + q4;
                bf[ni][0] = fbits(Bc[kk * BSTR + cc]);
                bf[ni][1] = fbits(Bc[(kk + 4) * BSTR + cc]);
            }
            #pragma unroll
            for (int mi = 0; mi < 4; mi++)
                #pragma unroll
                for (int ni = 0; ni < 8; ni++)
                    mma_tf32(acc[mi][ni], af[mi], bf[ni][0], bf[ni][1]);
        }
        __syncthreads();
    }

    // Epilogue
    #pragma unroll
    for (int mi = 0; mi < 4; mi++) {
        int r = m0 + wm * 64 + mi * 16 + gr;
        #pragma unroll
        for (int ni = 0; ni < 8; ni++) {
            int c = n0 + wn * 64 + ni * 8 + 2 * q4;
            if (MODE == 0) {
                // round here so flash streams exact tf32 values
                int b = r >> 11, ntk = r & (NSEQ - 1);
                int h = c >> 6, d = c & 63;
                float* p0 = out + ((size_t)((b * NH + h) * NSEQ + ntk)) * DHD + d;
                float* p1 = out + ((size_t)((b * NH + h) * NSEQ + ntk + 8)) * DHD + d;
                *(float2*)p0 = make_float2(tff(acc[mi][ni][0]), tff(acc[mi][ni][1]));
                *(float2*)p1 = make_float2(tff(acc[mi][ni][2]), tff(acc[mi][ni][3]));
            } else {
                float2 bv = *(const float2*)(bias + c);
                *(float2*)(out + (size_t)r * DIM + c) =
                    make_float2(acc[mi][ni][0] + bv.x, acc[mi][ni][1] + bv.y);
                *(float2*)(out + (size_t)(r + 8) * DIM + c) =
                    make_float2(acc[mi][ni][2] + bv.x, acc[mi][ni][3] + bv.y);
            }
        }
    }
}

// ---------------------------------------------------------------------------
// Flash attention v5b: 512 threads / 16 warps, 256 query rows, key tile 64.
// cp.async double-buffered K/V staging; plain row-major smem stride 68;
// k-relabel PV (A-frag = rounded S {s0,s2,s1,s3}, B rows 8kc+2q4, +1).
// Q/K/V arrive pre-rounded from gemm0; P rounded here; O rounded at epilogue.
// ---------------------------------------------------------------------------
constexpr int FST = 68;
constexpr int FKTILE = 64;
constexpr int FLASH_SMEM = (256 * FST + 2 * FKTILE * FST + 2 * FKTILE * FST) * 4;  // 139264 B

__global__ void __launch_bounds__(512, 1)
flash_attn()
{
    extern __shared__ float sm[];
    float* Qs = sm;                          // 256 x 68
    float* Ks = Qs + 256 * FST;              // 2 x 64 x 68
    float* Vs = Ks + 2 * FKTILE * FST;       // 2 x 64 x 68
    const uint32_t Ks_u = (uint32_t)__cvta_generic_to_shared(Ks);
    const uint32_t Vs_u = (uint32_t)__cvta_generic_to_shared(Vs);

    const int bh    = blockIdx.y;
    const int qbase = blockIdx.x * 256;
    const float* Qg = g_Q + ((size_t)bh * NSEQ + qbase) * DHD;
    const float* Kg = g_K + (size_t)bh * NSEQ * DHD;
    const float* Vg = g_V + (size_t)bh * NSEQ * DHD;

    const int tid = threadIdx.x, lane = tid & 31, wid = tid >> 5;   // wid 0..15
    const int gr = lane >> 2, q4 = lane & 3;
    const int rbase = wid * 16;

    // ---- stage Q once (already tf32) ----
    #pragma unroll
    for (int j = 0; j < 8; j++) {
        int ch = tid + j * 512;          // 0..4095
        int r = ch >> 4, c4 = ch & 15;
        *(float4*)(Qs + r * FST + c4 * 4) =
            *(const float4*)(Qg + (size_t)r * DHD + c4 * 4);
    }

    float o[8][4];
    #pragma unroll
    for (int nt = 0; nt < 8; nt++)
        #pragma unroll
        for (int v = 0; v < 4; v++) o[nt][v] = 0.f;
    float mr[2] = {-INFINITY, -INFINITY};
    float lr[2] = {0.f, 0.f};

    auto issueKV = [&](int it) {
        const int buf = it & 1;
        const float* Kp = Kg + (size_t)it * FKTILE * DHD;
        const float* Vp = Vg + (size_t)it * FKTILE * DHD;
        #pragma unroll
        for (int j = 0; j < 2; j++) {
            int ch = tid + j * 512;      // 0..1023
            int r = ch >> 4, c4 = ch & 15;
            uint32_t off = (uint32_t)(buf * FKTILE * FST + r * FST + c4 * 4) * 4;
            cp16(Ks_u + off, Kp + (size_t)r * DHD + c4 * 4);
            cp16(Vs_u + off, Vp + (size_t)r * DHD + c4 * 4);
        }
        cp_commit();
    };

    issueKV(0);

    const int NIT = NSEQ / FKTILE;   // 32
    #pragma unroll 1
    for (int it = 0; it < NIT; ++it) {
        if (it + 1 < NIT) { issueKV(it + 1); cp_wait<1>(); }
        else              { cp_wait<0>(); }
        __syncthreads();

        const float* Kc = Ks + (it & 1) * FKTILE * FST;
        const float* Vc = Vs + (it & 1) * FKTILE * FST;

        // ---- S = Q K^T over 64 keys ----
        float s[8][4];
        #pragma unroll
        for (int nt = 0; nt < 8; nt++)
            #pragma unroll
            for (int v = 0; v < 4; v++) s[nt][v] = 0.f;

        #pragma unroll
        for (int kc = 0; kc < 8; kc++) {
            uint32_t qf[4];
            const int r = rbase + gr, c = kc * 8 + q4;
            qf[0] = fbits(Qs[r * FST + c]);
            qf[1] = fbits(Qs[(r + 8) * FST + c]);
            qf[2] = fbits(Qs[r * FST + c + 4]);
            qf[3] = fbits(Qs[(r + 8) * FST + c + 4]);
            #pragma unroll
            for (int nt = 0; nt < 8; nt++) {
                const int n = nt * 8 + gr;
                mma_tf32(s[nt], qf, fbits(Kc[n * FST + c]), fbits(Kc[n * FST + c + 4]));
            }
        }

        // ---- online softmax (rows gr / gr+8) ----
        #pragma unroll
        for (int rr = 0; rr < 2; rr++) {
            const int i0 = 2 * rr;
            float tm = -INFINITY;
            #pragma unroll
            for (int nt = 0; nt < 8; nt++)
                tm = fmaxf(tm, fmaxf(s[nt][i0], s[nt][i0 + 1]));
            tm = fmaxf(tm, __shfl_xor_sync(0xffffffffu, tm, 1));
            tm = fmaxf(tm, __shfl_xor_sync(0xffffffffu, tm, 2));
            float mnew  = fmaxf(mr[rr], tm);
            float alpha = ex2((mr[rr] - mnew) * CEXP);
            mr[rr] = mnew;
            float ps = 0.f;
            #pragma unroll
            for (int nt = 0; nt < 8; nt++) {
                float p0 = ex2((s[nt][i0] - mnew) * CEXP);
                float p1 = ex2((s[nt][i0 + 1] - mnew) * CEXP);
                s[nt][i0] = p0; s[nt][i0 + 1] = p1;
                ps += p0 + p1;
            }
            ps += __shfl_xor_sync(0xffffffffu, ps, 1);
            ps += __shfl_xor_sync(0xffffffffu, ps, 2);
            lr[rr] = lr[rr] * alpha + ps;
            #pragma unroll
            for (int nt = 0; nt < 8; nt++) {
                o[nt][i0] *= alpha;
                o[nt][i0 + 1] *= alpha;
            }
        }

        // ---- O += P V (k-relabel), P rounded to tf32 ----
        #pragma unroll
        for (int kc = 0; kc < 8; kc++) {
            uint32_t a[4];
            a[0] = f2tf(s[kc][0]);
            a[1] = f2tf(s[kc][2]);
            a[2] = f2tf(s[kc][1]);
            a[3] = f2tf(s[kc][3]);
            const int k0r = kc * 8 + 2 * q4;
            #pragma unroll
            for (int nt = 0; nt < 8; nt++) {
                const int n = nt * 8 + gr;
                mma_tf32(o[nt], a,
                         fbits(Vc[k0r * FST + n]),
                         fbits(Vc[(k0r + 1) * FST + n]));
            }
        }
        __syncthreads();
    }

    // ---- epilogue: O /= l, round, -> g_O [B,N,H*DH] ----
    const int b = bh / NH, h = bh % NH;
    float* Og = g_O + ((size_t)(b * NSEQ + qbase)) * INNER + h * DHD;
    const int r0 = rbase + gr;
    const float inv0 = 1.f / lr[0];
    const float inv1 = 1.f / lr[1];
    #pragma unroll
    for (int nt = 0; nt < 8; nt++) {
        int d = nt * 8 + 2 * q4;
        *(float2*)(Og + (size_t)r0 * INNER + d) =
            make_float2(tff(o[nt][0] * inv0), tff(o[nt][1] * inv0));
        *(float2*)(Og + (size_t)(r0 + 8) * INNER + d) =
            make_float2(tff(o[nt][2] * inv1), tff(o[nt][3] * inv1));
    }
}

// ---------------------------------------------------------------------------
// Launch
// ---------------------------------------------------------------------------
extern "C" void kernel_launch(void* const* d_in, const int* in_sizes, int n_in,
                              void* d_out, int out_size) {
    (void)in_sizes; (void)n_in; (void)out_size;
    const float* x  = (const float*)d_in[0];
    const float* Wq = (const float*)d_in[1];
    const float* Wk = (const float*)d_in[2];
    const float* Wv = (const float*)d_in[3];
    const float* Wo = (const float*)d_in[4];
    const float* bo = (const float*)d_in[5];
    float* out = (float*)d_out;

    cudaFuncSetAttribute(gemm_tf32<0>, cudaFuncAttributeMaxDynamicSharedMemorySize, GEMM_SMEM);
    cudaFuncSetAttribute(gemm_tf32<1>, cudaFuncAttributeMaxDynamicSharedMemorySize, GEMM_SMEM);
    cudaFuncSetAttribute(flash_attn,   cudaFuncAttributeMaxDynamicSharedMemorySize, FLASH_SMEM);

    float* gX;  cudaGetSymbolAddress((void**)&gX,  g_X);
    float* gWq; cudaGetSymbolAddress((void**)&gWq, g_Wq);
    float* gWk; cudaGetSymbolAddress((void**)&gWk, g_Wk);
    float* gWv; cudaGetSymbolAddress((void**)&gWv, g_Wv);
    float* gWo; cudaGetSymbolAddress((void**)&gWo, g_Wo);

    // 0) pre-round inputs to tf32 (rna) so hot loops need no cvt
    round_tf32<<<2048, 256>>>(x,  gX,  MTOK * DIM / 4);
    round_tf32<<<1024, 256>>>(Wq, gWq, DIM * INNER / 4);
    round_tf32<<<1024, 256>>>(Wk, gWk, DIM * INNER / 4);
    round_tf32<<<1024, 256>>>(Wv, gWv, DIM * INNER / 4);
    round_tf32<<<1024, 256>>>(Wo, gWo, INNER * DIM / 4);

    // 1) Q/K/V projections
    gemm_tf32<0><<<dim3(INNER / BN, MTOK / BM, 3), 128, GEMM_SMEM>>>(nullptr, nullptr);
    // 2) attention
    flash_attn<<<dim3(NSEQ / 256, BATCH * NH), 512, FLASH_SMEM>>>();
    // 3) output projection + bias
    gemm_tf32<1><<<dim3(DIM / BN, MTOK / BM, 1), 128, GEMM_SMEM>>>(bo, out);
}

// round 16
// speedup vs baseline: 1.2296x; 1.0401x over previous
#include <cuda_runtime.h>
#include <cstdint>
#include <cmath>

namespace {
constexpr int BATCH = 4, NSEQ = 2048, DIM = 1024, NH = 16, DHD = 64, INNER = 1024;
constexpr int MTOK = BATCH * NSEQ;
constexpr float CEXP = 0.125f * 1.4426950408889634f;
}

// Scratch (allocation-free rule: __device__ globals)
__device__ __align__(256) float g_Q[MTOK * INNER];   // [B,H,N,DH]  (tf32-rounded)
__device__ __align__(256) float g_K[MTOK * INNER];   // [B,H,N,DH]  (tf32-rounded)
__device__ __align__(256) float g_V[MTOK * INNER];   // [B,H,N,DH]  (tf32-rounded)
__device__ __align__(256) float g_O[MTOK * INNER];   // [B,N,H*DH]  (tf32-rounded)
__device__ __align__(256) float g_X [MTOK * DIM];    // rna(x)
__device__ __align__(256) float g_Wq[DIM * INNER];   // rna(Wq)
__device__ __align__(256) float g_Wk[DIM * INNER];
__device__ __align__(256) float g_Wv[DIM * INNER];
__device__ __align__(256) float g_Wo[INNER * DIM];

__device__ __forceinline__ uint32_t f2tf(float x) {
    uint32_t u;
    asm("cvt.rna.tf32.f32 %0, %1;" : "=r"(u) : "f"(x));
    return u;
}
__device__ __forceinline__ float tff(float x) { return __uint_as_float(f2tf(x)); }
__device__ __forceinline__ uint32_t fbits(float x) { return __float_as_uint(x); }
__device__ __forceinline__ float ex2(float x) {
    float y;
    asm("ex2.approx.ftz.f32 %0, %1;" : "=f"(y) : "f"(x));
    return y;
}

// D += A(16x8) * B(8x8), tf32 (operands pre-rounded; HW truncation = identity)
__device__ __forceinline__ void mma_tf32(float* d, const uint32_t* a, uint32_t b0, uint32_t b1) {
    asm volatile(
        "mma.sync.aligned.m16n8k8.row.col.f32.tf32.tf32.f32 "
        "{%0,%1,%2,%3}, {%4,%5,%6,%7}, {%8,%9}, {%0,%1,%2,%3};"
        : "+f"(d[0]), "+f"(d[1]), "+f"(d[2]), "+f"(d[3])
        : "r"(a[0]), "r"(a[1]), "r"(a[2]), "r"(a[3]), "r"(b0), "r"(b1));
}

// cp.async helpers
__device__ __forceinline__ void cp16(uint32_t dst, const void* src) {
    asm volatile("cp.async.cg.shared.global [%0], [%1], 16;" :: "r"(dst), "l"(src));
}
__device__ __forceinline__ void cp_commit() { asm volatile("cp.async.commit_group;"); }
template <int N>
__device__ __forceinline__ void cp_wait() { asm volatile("cp.async.wait_group %0;" :: "n"(N)); }

// ---------------------------------------------------------------------------
// Fused pre-round pass: one launch rounds x, Wq, Wk, Wv, Wo into scratch.
// ---------------------------------------------------------------------------
constexpr int X4  = MTOK * DIM / 4;      // 2,097,152 float4
constexpr int W4  = DIM * INNER / 4;     //   262,144 float4
constexpr int TOT4 = X4 + 4 * W4;        // 3,145,728

__global__ void __launch_bounds__(256)
round_all(const float* __restrict__ x,
          const float* __restrict__ wq, const float* __restrict__ wk,
          const float* __restrict__ wv, const float* __restrict__ wo)
{
    int i = blockIdx.x * 256 + threadIdx.x;
    const int stride = gridDim.x * 256;
    for (; i < TOT4; i += stride) {
        const float4* src;
        float4* dst;
        if (i < X4) {
            src = (const float4*)x + i;
            dst = (float4*)g_X + i;
        } else {
            int j = i - X4;
            int w = j >> 18;            // 0..3
            int off = j & (W4 - 1);
            const float* sp = (w == 0) ? wq : (w == 1) ? wk : (w == 2) ? wv : wo;
            float* dp = (w == 0) ? g_Wq : (w == 1) ? g_Wk : (w == 2) ? g_Wv : g_Wo;
            src = (const float4*)sp + off;
            dst = (float4*)dp + off;
        }
        float4 v = *src;
        v.x = tff(v.x); v.y = tff(v.y); v.z = tff(v.z); v.w = tff(v.w);
        *dst = v;
    }
}

// ---------------------------------------------------------------------------
// GEMM v3: C[8192,1024] = X @ W.  CTA 128x128x32, 128 threads (4 warps of
// 64x64).  cp.async 2-stage; operands pre-rounded.
// k-relabel (kappa=q4 -> 2q4, kappa=q4+4 -> 2q4+1): A-frag = 2x LDS.64,
// B-frag rows (8ks+2q4, +1).  ASTR=40 / BSTR=132 conflict-free.
// MODE 0: QKV projections (blockIdx.z), epilogue rounds outputs.
// MODE 1: out-proj + bias -> d_out.
// ---------------------------------------------------------------------------
constexpr int BM = 128, BN = 128, BK = 32;
constexpr int ASTR = 40;    // pair-load pattern {8gr+2q4} conflict-free
constexpr int BSTR = 132;   // row-pair pattern {8q4+gr} conflict-free
constexpr int GEMM_SMEM = (2 * BM * ASTR + 2 * BK * BSTR) * 4;   // 74752 B

template <int MODE>
__global__ void __launch_bounds__(128)
gemm_tf32(const float* __restrict__ bias, float* __restrict__ outp)
{
    extern __shared__ float sm[];
    float* As = sm;                      // [2][128][40]
    float* Bs = sm + 2 * BM * ASTR;      // [2][32][132]
    const uint32_t As_u = (uint32_t)__cvta_generic_to_shared(As);
    const uint32_t Bs_u = (uint32_t)__cvta_generic_to_shared(Bs);

    const int m0 = blockIdx.y * BM;
    const int n0 = blockIdx.x * BN;

    const float* X;
    const float* W;
    float* out;
    if (MODE == 0) {
        X = g_X;
        if (blockIdx.z == 0)      { W = g_Wq; out = g_Q; }
        else if (blockIdx.z == 1) { W = g_Wk; out = g_K; }
        else                      { W = g_Wv; out = g_V; }
    } else {
        X = g_O;
        W = g_Wo;
        out = outp;
    }

    const int tid  = threadIdx.x;
    const int lane = tid & 31;
    const int wid  = tid >> 5;
    const int wm   = wid >> 1;    // 0..1
    const int wn   = wid & 1;     // 0..1
    const int gr   = lane >> 2;
    const int q4   = lane & 3;

    float acc[4][8][4];
    #pragma unroll
    for (int i = 0; i < 4; i++)
        #pragma unroll
        for (int j = 0; j < 8; j++)
            #pragma unroll
            for (int v = 0; v < 4; v++) acc[i][j][v] = 0.f;

    auto issue = [&](int kt) {
        const int k0 = kt * BK, buf = kt & 1;
        const uint32_t ab = As_u + buf * (BM * ASTR * 4);
        const uint32_t bb = Bs_u + buf * (BK * BSTR * 4);
        #pragma unroll
        for (int j = 0; j < 8; j++) {
            int ch = tid + j * 128;            // 0..1023
            int ar = ch >> 3, ac = ch & 7;     // A: 128 rows x 8 chunks
            cp16(ab + (uint32_t)(ar * ASTR + ac * 4) * 4,
                 X + (size_t)(m0 + ar) * 1024 + k0 + ac * 4);
        }
        #pragma unroll
        for (int j = 0; j < 8; j++) {
            int ch = tid + j * 128;
            int br = ch >> 5, bc = ch & 31;    // B: 32 rows x 32 chunks
            cp16(bb + (uint32_t)(br * BSTR + bc * 4) * 4,
                 W + (size_t)(k0 + br) * 1024 + n0 + bc * 4);
        }
        cp_commit();
    };

    issue(0);

    const int NKT = DIM / BK;   // 32
    #pragma unroll 1
    for (int kt = 0; kt < NKT; ++kt) {
        if (kt + 1 < NKT) { issue(kt + 1); cp_wait<1>(); }
        else              { cp_wait<0>(); }
        __syncthreads();

        const float* Ac = As + (kt & 1) * BM * ASTR;
        const float* Bc = Bs + (kt & 1) * BK * BSTR;

        #pragma unroll
        for (int ks = 0; ks < 4; ++ks) {
            const int c = ks * 8 + 2 * q4;     // relabeled k column (even)
            uint32_t af[4][4], bf[8][2];
            #pragma unroll
            for (int mi = 0; mi < 4; mi++) {
                int r = wm * 64 + mi * 16 + gr;
                float2 l0 = *(const float2*)(Ac + r * ASTR + c);
                float2 l1 = *(const float2*)(Ac + (r + 8) * ASTR + c);
                af[mi][0] = fbits(l0.x);
                af[mi][1] = fbits(l1.x);
                af[mi][2] = fbits(l0.y);
                af[mi][3] = fbits(l1.y);
            }
            #pragma unroll
            for (int ni = 0; ni < 8; ni++) {
                int cc = wn * 64 + ni * 8 + gr;
                bf[ni][0] = fbits(Bc[c * BSTR + cc]);
                bf[ni][1] = fbits(Bc[(c + 1) * BSTR + cc]);
            }
            #pragma unroll
            for (int mi = 0; mi < 4; mi++)
                #pragma unroll
                for (int ni = 0; ni < 8; ni++)
                    mma_tf32(acc[mi][ni], af[mi], bf[ni][0], bf[ni][1]);
        }
        __syncthreads();
    }

    // Epilogue
    #pragma unroll
    for (int mi = 0; mi < 4; mi++) {
        int r = m0 + wm * 64 + mi * 16 + gr;
        #pragma unroll
        for (int ni = 0; ni < 8; ni++) {
            int c = n0 + wn * 64 + ni * 8 + 2 * q4;
            if (MODE == 0) {
                int b = r >> 11, ntk = r & (NSEQ - 1);
                int h = c >> 6, d = c & 63;
                float* p0 = out + ((size_t)((b * NH + h) * NSEQ + ntk)) * DHD + d;
                float* p1 = out + ((size_t)((b * NH + h) * NSEQ + ntk + 8)) * DHD + d;
                *(float2*)p0 = make_float2(tff(acc[mi][ni][0]), tff(acc[mi][ni][1]));
                *(float2*)p1 = make_float2(tff(acc[mi][ni][2]), tff(acc[mi][ni][3]));
            } else {
                float2 bv = *(const float2*)(bias + c);
                *(float2*)(out + (size_t)r * DIM + c) =
                    make_float2(acc[mi][ni][0] + bv.x, acc[mi][ni][1] + bv.y);
                *(float2*)(out + (size_t)(r + 8) * DIM + c) =
                    make_float2(acc[mi][ni][2] + bv.x, acc[mi][ni][3] + bv.y);
            }
        }
    }
}

// ---------------------------------------------------------------------------
// Flash attention v6: 512 threads / 16 warps, 256 query rows, key tile 64.
// cp.async double-buffered K/V; S-phase k-relabel -> Q-frag 2x LDS.64,
// K-frag 1x LDS.64 (Q/K stride 72, pattern {8gr+2q4} conflict-free);
// PV k-relabel as before (V stride 68, pattern {8q4+gr} conflict-free).
// Q/K/V pre-rounded by gemm0; P rounded here; O rounded at epilogue.
// ---------------------------------------------------------------------------
constexpr int QKS = 72;
constexpr int VST = 68;
constexpr int FKTILE = 64;
constexpr int FLASH_SMEM =
    (256 * QKS + 2 * FKTILE * QKS + 2 * FKTILE * VST) * 4;   // 145408 B

__global__ void __launch_bounds__(512, 1)
flash_attn()
{
    extern __shared__ float sm[];
    float* Qs = sm;                          // 256 x 72
    float* Ks = Qs + 256 * QKS;              // 2 x 64 x 72
    float* Vs = Ks + 2 * FKTILE * QKS;       // 2 x 64 x 68
    const uint32_t Ks_u = (uint32_t)__cvta_generic_to_shared(Ks);
    const uint32_t Vs_u = (uint32_t)__cvta_generic_to_shared(Vs);

    const int bh    = blockIdx.y;
    const int qbase = blockIdx.x * 256;
    const float* Qg = g_Q + ((size_t)bh * NSEQ + qbase) * DHD;
    const float* Kg = g_K + (size_t)bh * NSEQ * DHD;
    const float* Vg = g_V + (size_t)bh * NSEQ * DHD;

    const int tid = threadIdx.x, lane = tid & 31, wid = tid >> 5;   // wid 0..15
    const int gr = lane >> 2, q4 = lane & 3;
    const int rbase = wid * 16;

    // ---- stage Q once (already tf32), stride 72 ----
    #pragma unroll
    for (int j = 0; j < 8; j++) {
        int ch = tid + j * 512;          // 0..4095
        int r = ch >> 4, c4 = ch & 15;
        *(float4*)(Qs + r * QKS + c4 * 4) =
            *(const float4*)(Qg + (size_t)r * DHD + c4 * 4);
    }

    float o[8][4];
    #pragma unroll
    for (int nt = 0; nt < 8; nt++)
        #pragma unroll
        for (int v = 0; v < 4; v++) o[nt][v] = 0.f;
    float mr[2] = {-INFINITY, -INFINITY};
    float lr[2] = {0.f, 0.f};

    auto issueKV = [&](int it) {
        const int buf = it & 1;
        const float* Kp = Kg + (size_t)it * FKTILE * DHD;
        const float* Vp = Vg + (size_t)it * FKTILE * DHD;
        #pragma unroll
        for (int j = 0; j < 2; j++) {
            int ch = tid + j * 512;      // 0..1023
            int r = ch >> 4, c4 = ch & 15;
            cp16(Ks_u + (uint32_t)(buf * FKTILE * QKS + r * QKS + c4 * 4) * 4,
                 Kp + (size_t)r * DHD + c4 * 4);
            cp16(Vs_u + (uint32_t)(buf * FKTILE * VST + r * VST + c4 * 4) * 4,
                 Vp + (size_t)r * DHD + c4 * 4);
        }
        cp_commit();
    };

    issueKV(0);

    const int NIT = NSEQ / FKTILE;   // 32
    #pragma unroll 1
    for (int it = 0; it < NIT; ++it) {
        if (it + 1 < NIT) { issueKV(it + 1); cp_wait<1>(); }
        else              { cp_wait<0>(); }
        __syncthreads();

        const float* Kc = Ks + (it & 1) * FKTILE * QKS;
        const float* Vc = Vs + (it & 1) * FKTILE * VST;

        // ---- S = Q K^T over 64 keys (k-relabel: pair loads) ----
        float s[8][4];
        #pragma unroll
        for (int nt = 0; nt < 8; nt++)
            #pragma unroll
            for (int v = 0; v < 4; v++) s[nt][v] = 0.f;

        #pragma unroll
        for (int kc = 0; kc < 8; kc++) {
            const int c = kc * 8 + 2 * q4;   // relabeled k column (even)
            uint32_t qf[4];
            {
                const int r = rbase + gr;
                float2 l0 = *(const float2*)(Qs + r * QKS + c);
                float2 l1 = *(const float2*)(Qs + (r + 8) * QKS + c);
                qf[0] = fbits(l0.x);
                qf[1] = fbits(l1.x);
                qf[2] = fbits(l0.y);
                qf[3] = fbits(l1.y);
            }
            #pragma unroll
            for (int nt = 0; nt < 8; nt++) {
                const int n = nt * 8 + gr;
                float2 kb = *(const float2*)(Kc + n * QKS + c);
                mma_tf32(s[nt], qf, fbits(kb.x), fbits(kb.y));
            }
        }

        // ---- online softmax (rows gr / gr+8) ----
        #pragma unroll
        for (int rr = 0; rr < 2; rr++) {
            const int i0 = 2 * rr;
            float tm = -INFINITY;
            #pragma unroll
            for (int nt = 0; nt < 8; nt++)
                tm = fmaxf(tm, fmaxf(s[nt][i0], s[nt][i0 + 1]));
            tm = fmaxf(tm, __shfl_xor_sync(0xffffffffu, tm, 1));
            tm = fmaxf(tm, __shfl_xor_sync(0xffffffffu, tm, 2));
            float mnew  = fmaxf(mr[rr], tm);
            float alpha = ex2((mr[rr] - mnew) * CEXP);
            mr[rr] = mnew;
            float ps = 0.f;
            #pragma unroll
            for (int nt = 0; nt < 8; nt++) {
                float p0 = ex2((s[nt][i0] - mnew) * CEXP);
                float p1 = ex2((s[nt][i0 + 1] - mnew) * CEXP);
                s[nt][i0] = p0; s[nt][i0 + 1] = p1;
                ps += p0 + p1;
            }
            ps += __shfl_xor_sync(0xffffffffu, ps, 1);
            ps += __shfl_xor_sync(0xffffffffu, ps, 2);
            lr[rr] = lr[rr] * alpha + ps;
            #pragma unroll
            for (int nt = 0; nt < 8; nt++) {
                o[nt][i0] *= alpha;
                o[nt][i0 + 1] *= alpha;
            }
        }

        // ---- O += P V (k-relabel), P rounded to tf32 ----
        #pragma unroll
        for (int kc = 0; kc < 8; kc++) {
            uint32_t a[4];
            a[0] = f2tf(s[kc][0]);
            a[1] = f2tf(s[kc][2]);
            a[2] = f2tf(s[kc][1]);
            a[3] = f2tf(s[kc][3]);
            const int k0r = kc * 8 + 2 * q4;
            #pragma unroll
            for (int nt = 0; nt < 8; nt++) {
                const int n = nt * 8 + gr;
                mma_tf32(o[nt], a,
                         fbits(Vc[k0r * VST + n]),
                         fbits(Vc[(k0r + 1) * VST + n]));
            }
        }
        __syncthreads();
    }

    // ---- epilogue: O /= l, round, -> g_O [B,N,H*DH] ----
    const int b = bh / NH, h = bh % NH;
    float* Og = g_O + ((size_t)(b * NSEQ + qbase)) * INNER + h * DHD;
    const int r0 = rbase + gr;
    const float inv0 = 1.f / lr[0];
    const float inv1 = 1.f / lr[1];
    #pragma unroll
    for (int nt = 0; nt < 8; nt++) {
        int d = nt * 8 + 2 * q4;
        *(float2*)(Og + (size_t)r0 * INNER + d) =
            make_float2(tff(o[nt][0] * inv0), tff(o[nt][1] * inv0));
        *(float2*)(Og + (size_t)(r0 + 8) * INNER + d) =
            make_float2(tff(o[nt][2] * inv1), tff(o[nt][3] * inv1));
    }
}

// ---------------------------------------------------------------------------
// Launch
// ---------------------------------------------------------------------------
extern "C" void kernel_launch(void* const* d_in, const int* in_sizes, int n_in,
                              void* d_out, int out_size) {
    (void)in_sizes; (void)n_in; (void)out_size;
    const float* x  = (const float*)d_in[0];
    const float* Wq = (const float*)d_in[1];
    const float* Wk = (const float*)d_in[2];
    const float* Wv = (const float*)d_in[3];
    const float* Wo = (const float*)d_in[4];
    const float* bo = (const float*)d_in[5];
    float* out = (float*)d_out;

    cudaFuncSetAttribute(gemm_tf32<0>, cudaFuncAttributeMaxDynamicSharedMemorySize, GEMM_SMEM);
    cudaFuncSetAttribute(gemm_tf32<1>, cudaFuncAttributeMaxDynamicSharedMemorySize, GEMM_SMEM);
    cudaFuncSetAttribute(flash_attn,   cudaFuncAttributeMaxDynamicSharedMemorySize, FLASH_SMEM);

    // 0) single fused pre-round pass (rna tf32)
    round_all<<<2048, 256>>>(x, Wq, Wk, Wv, Wo);
    // 1) Q/K/V projections
    gemm_tf32<0><<<dim3(INNER / BN, MTOK / BM, 3), 128, GEMM_SMEM>>>(nullptr, nullptr);
    // 2) attention
    flash_attn<<<dim3(NSEQ / 256, BATCH * NH), 512, FLASH_SMEM>>>();
    // 3) output projection + bias
    gemm_tf32<1><<<dim3(DIM / BN, MTOK / BM, 1), 128, GEMM_SMEM>>>(bo, out);
}